// round 15
// baseline (speedup 1.0000x reference)
#include <cuda_runtime.h>
#include <cuda_fp16.h>
#include <stdint.h>
#include <math.h>

// Problem constants
#define BATCH 4
#define SEQ   2048
#define DIM   1024
#define NHEAD 16
#define HDIM  64
#define FFDIM 4096
#define MROWS (BATCH*SEQ)   // 8192

// ==================== static device scratch (no runtime allocs) ============
__device__ float g_x2 [(size_t)MROWS * DIM];             // post-attn residual fp32
__device__ __half g_qkv[(size_t)MROWS * 3 * DIM];        // qkv fp16 (q scaled log2e/8)
__device__ __half g_h  [(size_t)MROWS * DIM];            // LN out fp16
__device__ __half g_att[(size_t)MROWS * DIM];            // attention out fp16
__device__ __half g_ffn[(size_t)MROWS * FFDIM];          // gelu(fc1) fp16
// transposed weights: [N, K] fp16
__device__ __half g_wq[(size_t)3*DIM * DIM];
__device__ __half g_wo[(size_t)DIM * DIM];
__device__ __half g_w1[(size_t)FFDIM * DIM];
__device__ __half g_w2[(size_t)DIM * FFDIM];

// ==================== helpers ==============================================
__device__ __forceinline__ uint32_t smem_u32(const void* p) {
    uint32_t a;
    asm("{ .reg .u64 t; cvta.to.shared.u64 t, %1; cvt.u32.u64 %0, t; }" : "=r"(a) : "l"(p));
    return a;
}

__device__ __forceinline__ float ex2f(float x) {
    float r;
    asm("ex2.approx.ftz.f32 %0, %1;" : "=f"(r) : "f"(x));
    return r;
}

// packed half2 exp2: d = 2^a (elementwise)
__device__ __forceinline__ uint32_t ex2_h2(uint32_t a) {
    uint32_t r;
    asm("ex2.approx.f16x2 %0, %1;" : "=r"(r) : "r"(a));
    return r;
}

__device__ __forceinline__ uint32_t hadd2u(uint32_t a, uint32_t b) {
    uint32_t r;
    asm("add.f16x2 %0, %1, %2;" : "=r"(r) : "r"(a), "r"(b));
    return r;
}

#define CP_ASYNC16(saddr, gptr) \
    asm volatile("cp.async.cg.shared.global [%0], [%1], 16;" \
        :: "r"(saddr), "l"((const void*)(gptr)))
#define CP_COMMIT() asm volatile("cp.async.commit_group;" ::: "memory")
#define CP_WAIT0()  asm volatile("cp.async.wait_group 0;" ::: "memory")
#define CP_WAIT1()  asm volatile("cp.async.wait_group 1;" ::: "memory")

#define LDSM_X4(r0, r1, r2, r3, addr) \
    asm volatile("ldmatrix.sync.aligned.m8n8.x4.shared.b16 {%0,%1,%2,%3}, [%4];" \
        : "=r"(r0), "=r"(r1), "=r"(r2), "=r"(r3) : "r"(addr))

#define LDSM_X4_T(r0, r1, r2, r3, addr) \
    asm volatile("ldmatrix.sync.aligned.m8n8.x4.trans.shared.b16 {%0,%1,%2,%3}, [%4];" \
        : "=r"(r0), "=r"(r1), "=r"(r2), "=r"(r3) : "r"(addr))

#define MMA_F16(d, a, b0v, b1v) \
    asm volatile("mma.sync.aligned.m16n8k16.row.col.f32.f16.f16.f32 " \
        "{%0,%1,%2,%3}, {%4,%5,%6,%7}, {%8,%9}, {%0,%1,%2,%3};" \
        : "+f"((d)[0]), "+f"((d)[1]), "+f"((d)[2]), "+f"((d)[3]) \
        : "r"((a)[0]), "r"((a)[1]), "r"((a)[2]), "r"((a)[3]), "r"(b0v), "r"(b1v))

__device__ __forceinline__ uint32_t pack_h2(float x, float y) {
    __half2 h = __floats2half2_rn(x, y);
    return *reinterpret_cast<uint32_t*>(&h);
}

// ==================== weight transpose + fp16 convert (vectorized) =========
__global__ void __launch_bounds__(256)
wsplit_kernel(const float* __restrict__ W, __half* __restrict__ Th, int K, int N)
{
    __shared__ float tile[32][33];
    const int bx = blockIdx.x, by = blockIdx.y;
    const int tx = threadIdx.x & 31, ty = threadIdx.x >> 5;
    #pragma unroll
    for (int r = 0; r < 32; r += 8) {
        const int k = by * 32 + ty + r, n = bx * 32 + tx;
        tile[ty + r][tx] = W[(size_t)k * N + n];
    }
    __syncthreads();
    const int kx = (threadIdx.x & 15) * 2;
    const int ny = threadIdx.x >> 4;
    #pragma unroll
    for (int r = 0; r < 32; r += 16) {
        const int n = bx * 32 + ny + r;
        const int k = by * 32 + kx;
        __half2 hv = __floats2half2_rn(tile[kx][ny + r], tile[kx + 1][ny + r]);
        *reinterpret_cast<__half2*>(Th + (size_t)n * K + k) = hv;
    }
}

// ==================== LayerNorm (emits fp16) ===============================
__global__ void __launch_bounds__(256)
ln_kernel(const float* __restrict__ x, const float* __restrict__ g,
          const float* __restrict__ bta, __half* __restrict__ ohi)
{
    const int row = blockIdx.x;
    const int t = threadIdx.x;
    const float* xr = x + (size_t)row * DIM;

    float4 v = *reinterpret_cast<const float4*>(xr + t * 4);
    float s = v.x + v.y + v.z + v.w;
    float q = v.x * v.x + v.y * v.y + v.z * v.z + v.w * v.w;

    #pragma unroll
    for (int o = 16; o; o >>= 1) {
        s += __shfl_xor_sync(0xffffffffu, s, o);
        q += __shfl_xor_sync(0xffffffffu, q, o);
    }
    __shared__ float red[2][8];
    const int w = t >> 5, l = t & 31;
    if (l == 0) { red[0][w] = s; red[1][w] = q; }
    __syncthreads();
    if (t < 32) {
        s = (t < 8) ? red[0][t] : 0.f;
        q = (t < 8) ? red[1][t] : 0.f;
        #pragma unroll
        for (int o = 4; o; o >>= 1) {
            s += __shfl_xor_sync(0xffffffffu, s, o);
            q += __shfl_xor_sync(0xffffffffu, q, o);
        }
        if (t == 0) { red[0][0] = s; red[1][0] = q; }
    }
    __syncthreads();
    const float mean = red[0][0] * (1.f / DIM);
    const float var  = red[1][0] * (1.f / DIM) - mean * mean;
    const float rstd = rsqrtf(var + 1e-5f);

    float4 gv = *reinterpret_cast<const float4*>(g + t * 4);
    float4 bv = *reinterpret_cast<const float4*>(bta + t * 4);
    const float o0 = (v.x - mean) * rstd * gv.x + bv.x;
    const float o1 = (v.y - mean) * rstd * gv.y + bv.y;
    const float o2 = (v.z - mean) * rstd * gv.z + bv.z;
    const float o3 = (v.w - mean) * rstd * gv.w + bv.w;

    const size_t off = (size_t)row * DIM + t * 4;
    *reinterpret_cast<uint32_t*>(ohi + off)     = pack_h2(o0, o1);
    *reinterpret_cast<uint32_t*>(ohi + off + 2) = pack_h2(o2, o3);
}

// ==================== mma.sync GEMM (fp16, BK=64, 3-stage, persistent) =====
// C[M,N] = A[M,K] @ B^T, B [N,K] fp16 K-major. CTA 128x128, warp 64x32,
// 2 CTAs/SM, persistent tile loop; next-tile prologue overlaps epilogue.
enum { EPI_NONE = 0, EPI_BIAS_RESID = 1, EPI_BIAS_GELU = 2, EPI_QKV = 3 };

#define GROWB        144
#define STAGE_BYTES  (256 * GROWB)          // 36864
#define NSTAGE       3
#define GEMM_SMEM    (NSTAGE * STAGE_BYTES) // 110592
#define OFF_B        (128 * GROWB)          // 18432

template<int EPI>
__global__ void __launch_bounds__(256, 2)
tc_gemm_kernel(const __half* __restrict__ Ah, const __half* __restrict__ Bh,
               const float* __restrict__ bias, const float* __restrict__ R,
               float* __restrict__ Cf, __half* __restrict__ Ch,
               int M, int N, int K)
{
    extern __shared__ char smem[];
    const uint32_t sb = smem_u32(smem);
    const int tid = threadIdx.x;
    const int lane = tid & 31, wid = tid >> 5;

    const int nTilesX = N >> 7;
    const int nTiles = (M >> 7) * nTilesX;
    int tile = blockIdx.x;
    if (tile >= nTiles) return;

    int rowBase = (tile / nTilesX) * 128;
    int colBase = (tile % nTilesX) * 128;

    // issue 2 of the 8 load slices for chunk c into stage buffer
    auto load_slice = [&](int c, int stage, int half) {
        const int kbase = c * 64;
        const uint32_t stbase = sb + stage * STAGE_BYTES;
        #pragma unroll
        for (int i = half * 2; i < half * 2 + 2; i++) {
            const int idx = tid + i * 256;        // 0..2047
            const int row = idx >> 3;             // 0..255
            const int q = idx & 7;
            const uint32_t so = stbase + row * GROWB + q * 16;
            const __half* gp = (row < 128)
                ? (Ah + (size_t)(rowBase + row) * K + kbase + q * 8)
                : (Bh + (size_t)(colBase + row - 128) * K + kbase + q * 8);
            CP_ASYNC16(so, gp);
        }
    };
    auto load_stage = [&](int c, int stage) {
        #pragma unroll
        for (int hf = 0; hf < 4; hf++) load_slice(c, stage, hf);
        CP_COMMIT();
    };

    const int nChunks = K >> 6;

    const uint32_t a_off0 = ((wid >> 2) * 64 + (lane & 15)) * GROWB + ((lane >> 4) * 8) * 2;
    const uint32_t b_off0 = OFF_B + ((wid & 3) * 32 + (lane & 7) + ((lane >> 4) << 3)) * GROWB
                          + (((lane >> 3) & 1) * 8) * 2;

    // prologue for first tile
    load_stage(0, 0);
    load_stage(1, 1);

    while (true) {
        float acc[4][4][4];
        #pragma unroll
        for (int mt = 0; mt < 4; mt++)
            #pragma unroll
            for (int nt = 0; nt < 4; nt++)
                #pragma unroll
                for (int r = 0; r < 4; r++) acc[mt][nt][r] = 0.f;

        int stage = 0;
        for (int c = 0; c < nChunks; c++) {
            CP_WAIT1();
            __syncthreads();
            const bool more = (c + 2 < nChunks);
            int s2 = stage + 2; if (s2 >= NSTAGE) s2 -= NSTAGE;

            const uint32_t st = sb + stage * STAGE_BYTES;
            if (++stage == NSTAGE) stage = 0;

            #pragma unroll
            for (int ks = 0; ks < 4; ks++) {
                const uint32_t a_off = st + a_off0 + ks * 32;
                const uint32_t b_off = st + b_off0 + ks * 32;

                uint32_t a[4][4], b[8];
                #pragma unroll
                for (int mt = 0; mt < 4; mt++)
                    LDSM_X4(a[mt][0], a[mt][1], a[mt][2], a[mt][3],
                            a_off + mt * (16 * GROWB));
                LDSM_X4(b[0], b[1], b[2], b[3], b_off);
                LDSM_X4(b[4], b[5], b[6], b[7], b_off + 16 * GROWB);
                // spread next-chunk global->shared issues across ks steps
                if (more) load_slice(c + 2, s2, ks);
                #pragma unroll
                for (int mt = 0; mt < 4; mt++)
                    #pragma unroll
                    for (int nt = 0; nt < 4; nt++)
                        MMA_F16(acc[mt][nt], a[mt], b[nt * 2], b[nt * 2 + 1]);
            }
            CP_COMMIT();
        }

        __syncthreads();   // all LDSM reads done; smem reusable

        // save current tile's bases; start next tile's prologue under epilogue
        const int curRow = rowBase, curCol = colBase;
        const int next = tile + gridDim.x;
        const bool hasNext = (next < nTiles);
        if (hasNext) {
            rowBase = (next / nTilesX) * 128;
            colBase = (next % nTilesX) * 128;
            load_stage(0, 0);
            load_stage(1, 1);
        }

        // ------- epilogue (overlaps next tile's loads) -------
        #pragma unroll
        for (int mt = 0; mt < 4; mt++) {
            const int r0 = curRow + (wid >> 2) * 64 + mt * 16 + (lane >> 2);
            const int r1 = r0 + 8;
            #pragma unroll
            for (int nt = 0; nt < 4; nt++) {
                const int col = curCol + (wid & 3) * 32 + nt * 8 + (lane & 3) * 2;
                float v0 = acc[mt][nt][0], v1 = acc[mt][nt][1];
                float v2 = acc[mt][nt][2], v3 = acc[mt][nt][3];
                if (EPI == EPI_BIAS_RESID || EPI == EPI_BIAS_GELU) {
                    const float b0 = __ldg(bias + col), b1 = __ldg(bias + col + 1);
                    v0 += b0; v1 += b1; v2 += b0; v3 += b1;
                }
                if (EPI == EPI_QKV) {
                    // q: scale by log2(e)/8 so flash softmax can use exp2 directly
                    const float sc = (col < DIM) ? 0.18033688011112042f : 1.0f;
                    *reinterpret_cast<uint32_t*>(Ch + (size_t)r0 * N + col) = pack_h2(v0 * sc, v1 * sc);
                    *reinterpret_cast<uint32_t*>(Ch + (size_t)r1 * N + col) = pack_h2(v2 * sc, v3 * sc);
                } else if (EPI == EPI_BIAS_GELU) {
                    v0 = 0.5f * v0 * (1.f + erff(v0 * 0.70710678118654752f));
                    v1 = 0.5f * v1 * (1.f + erff(v1 * 0.70710678118654752f));
                    v2 = 0.5f * v2 * (1.f + erff(v2 * 0.70710678118654752f));
                    v3 = 0.5f * v3 * (1.f + erff(v3 * 0.70710678118654752f));
                    *reinterpret_cast<uint32_t*>(Ch + (size_t)r0 * N + col) = pack_h2(v0, v1);
                    *reinterpret_cast<uint32_t*>(Ch + (size_t)r1 * N + col) = pack_h2(v2, v3);
                } else {
                    if (EPI == EPI_BIAS_RESID) {
                        const float2 ra = *reinterpret_cast<const float2*>(R + (size_t)r0 * N + col);
                        const float2 rb = *reinterpret_cast<const float2*>(R + (size_t)r1 * N + col);
                        v0 += ra.x; v1 += ra.y; v2 += rb.x; v3 += rb.y;
                    }
                    float2 p0; p0.x = v0; p0.y = v1;
                    float2 p1; p1.x = v2; p1.y = v3;
                    *reinterpret_cast<float2*>(Cf + (size_t)r0 * N + col) = p0;
                    *reinterpret_cast<float2*>(Cf + (size_t)r1 * N + col) = p1;
                }
            }
        }

        if (!hasNext) break;
        tile = next;
    }
}

// ==================== Flash attention (fp16 1-pass, f16x2 exp2 softmax) ====
// CTA: 128 q-rows x 64 kv per iter, 8 warps x 16 q-rows. Causal. 2 CTAs/SM.
#define FROWB 144
#define FQ 0
#define FSTAGE0 (128*FROWB)                      // 18432
#define FS_K 0
#define FS_V (64*FROWB)
#define FSTAGE_BYTES (2*64*FROWB)                // 18432
#define FLASH_SMEM (FSTAGE0 + 2*FSTAGE_BYTES)    // 55296

__global__ void __launch_bounds__(256, 2)
flash_tc_kernel(const __half* __restrict__ qh, __half* __restrict__ ohi)
{
    extern __shared__ char smem[];
    const uint32_t sb = smem_u32(smem);
    const int qb = blockIdx.x;
    const int bh = blockIdx.y;
    const int b = bh >> 4, h = bh & 15;
    const int tid = threadIdx.x;
    const int lane = tid & 31, w = tid >> 5;
    const int rowStride = 3 * DIM;

    // load Q 128x64
    #pragma unroll
    for (int i = 0; i < 4; i++) {
        const int c = tid + i * 256;
        const int r = c >> 3, q = c & 7;
        const uint32_t so = r * FROWB + q * 16;
        const size_t go = (size_t)(b * SEQ + qb * 128 + r) * rowStride + h * HDIM + q * 8;
        CP_ASYNC16(sb + FQ + so, qh + go);
    }

    const int nkv = 2 * qb + 2;
    auto load_kv = [&](int j, int buf) {
        const uint32_t stb = sb + FSTAGE0 + buf * FSTAGE_BYTES;
        #pragma unroll
        for (int i = 0; i < 2; i++) {
            const int c = tid + i * 256;
            const int r = c >> 3, q = c & 7;
            const uint32_t so = r * FROWB + q * 16;
            const size_t gk = (size_t)(b * SEQ + j * 64 + r) * rowStride + DIM + h * HDIM + q * 8;
            CP_ASYNC16(stb + FS_K + so, qh + gk);
            CP_ASYNC16(stb + FS_V + so, qh + gk + DIM);
        }
        CP_COMMIT();
    };
    load_kv(0, 0);

    float O[8][4];
    #pragma unroll
    for (int nt = 0; nt < 8; nt++)
        #pragma unroll
        for (int r = 0; r < 4; r++) O[nt][r] = 0.f;
    float m0 = -1e30f, m1 = -1e30f, l0 = 0.f, l1 = 0.f;

    const int qr0 = qb * 128 + w * 16 + (lane >> 2);

    const int t8 = lane >> 3;
    const uint32_t q_row_off = (w * 16 + (lane & 15)) * FROWB;
    const uint32_t q_kadd = (lane >> 4) * 8;
    const uint32_t k_row = (t8 >> 1) * 8 + (lane & 7);
    const uint32_t k_hd = (t8 & 1) * 8;
    const uint32_t v_kv = (t8 & 1) * 8 + (lane & 7);
    const uint32_t v_nc = (t8 >> 1) * 8;

    for (int j = 0; j < nkv; j++) {
        CP_WAIT0();
        __syncthreads();
        if (j + 1 < nkv) load_kv(j + 1, (j + 1) & 1);
        const uint32_t st = sb + FSTAGE0 + (j & 1) * FSTAGE_BYTES;

        // ---- S = Q K^T (log2 domain) ----
        float s[8][4];
        #pragma unroll
        for (int nt = 0; nt < 8; nt++)
            #pragma unroll
            for (int r = 0; r < 4; r++) s[nt][r] = 0.f;

        #pragma unroll
        for (int ks = 0; ks < 4; ks++) {
            const uint32_t qoff = q_row_off + (ks * 16 + q_kadd) * 2;
            uint32_t a[4];
            LDSM_X4(a[0], a[1], a[2], a[3], sb + FQ + qoff);
            uint32_t kh[4][4];
            #pragma unroll
            for (int g = 0; g < 4; g++) {
                const uint32_t koff = (g * 16 + k_row) * FROWB + (ks * 16 + k_hd) * 2;
                LDSM_X4(kh[g][0], kh[g][1], kh[g][2], kh[g][3], st + FS_K + koff);
            }
            #pragma unroll
            for (int g = 0; g < 4; g++) {
                MMA_F16(s[2 * g],     a, kh[g][0], kh[g][1]);
                MMA_F16(s[2 * g + 1], a, kh[g][2], kh[g][3]);
            }
        }

        if (j >= 2 * qb) {
            const int kvb = j * 64;
            #pragma unroll
            for (int nt = 0; nt < 8; nt++) {
                const int kc = kvb + nt * 8 + (lane & 3) * 2;
                if (kc     > qr0)     s[nt][0] = -1e30f;
                if (kc + 1 > qr0)     s[nt][1] = -1e30f;
                if (kc     > qr0 + 8) s[nt][2] = -1e30f;
                if (kc + 1 > qr0 + 8) s[nt][3] = -1e30f;
            }
        }

        // ---- online softmax (packed f16x2 exp2) ----
        float mx0 = -1e30f, mx1 = -1e30f;
        #pragma unroll
        for (int nt = 0; nt < 8; nt++) {
            mx0 = fmaxf(mx0, fmaxf(s[nt][0], s[nt][1]));
            mx1 = fmaxf(mx1, fmaxf(s[nt][2], s[nt][3]));
        }
        mx0 = fmaxf(mx0, __shfl_xor_sync(0xffffffffu, mx0, 1));
        mx0 = fmaxf(mx0, __shfl_xor_sync(0xffffffffu, mx0, 2));
        mx1 = fmaxf(mx1, __shfl_xor_sync(0xffffffffu, mx1, 1));
        mx1 = fmaxf(mx1, __shfl_xor_sync(0xffffffffu, mx1, 2));
        const float nm0 = fmaxf(m0, mx0), nm1 = fmaxf(m1, mx1);
        const float sc0 = ex2f(m0 - nm0), sc1 = ex2f(m1 - nm1);
        m0 = nm0; m1 = nm1;

        uint32_t ph0[8], ph1[8];
        #pragma unroll
        for (int nt = 0; nt < 8; nt++) {
            ph0[nt] = ex2_h2(pack_h2(s[nt][0] - nm0, s[nt][1] - nm0));
            ph1[nt] = ex2_h2(pack_h2(s[nt][2] - nm1, s[nt][3] - nm1));
        }
        uint32_t t0s = hadd2u(hadd2u(hadd2u(ph0[0], ph0[1]), hadd2u(ph0[2], ph0[3])),
                              hadd2u(hadd2u(ph0[4], ph0[5]), hadd2u(ph0[6], ph0[7])));
        uint32_t t1s = hadd2u(hadd2u(hadd2u(ph1[0], ph1[1]), hadd2u(ph1[2], ph1[3])),
                              hadd2u(hadd2u(ph1[4], ph1[5]), hadd2u(ph1[6], ph1[7])));
        const __half2 h0s = *reinterpret_cast<__half2*>(&t0s);
        const __half2 h1s = *reinterpret_cast<__half2*>(&t1s);
        float r0 = __low2float(h0s) + __high2float(h0s);
        float r1 = __low2float(h1s) + __high2float(h1s);
        r0 += __shfl_xor_sync(0xffffffffu, r0, 1);
        r0 += __shfl_xor_sync(0xffffffffu, r0, 2);
        r1 += __shfl_xor_sync(0xffffffffu, r1, 1);
        r1 += __shfl_xor_sync(0xffffffffu, r1, 2);
        l0 = l0 * sc0 + r0;
        l1 = l1 * sc1 + r1;
        #pragma unroll
        for (int nt = 0; nt < 8; nt++) {
            O[nt][0] *= sc0; O[nt][1] *= sc0;
            O[nt][2] *= sc1; O[nt][3] *= sc1;
        }

        // ---- O += P V (P fragments already packed) ----
        #pragma unroll
        for (int ks = 0; ks < 4; ks++) {
            const int t0 = 2 * ks, t1 = 2 * ks + 1;
            uint32_t phi[4];
            phi[0] = ph0[t0];
            phi[1] = ph1[t0];
            phi[2] = ph0[t1];
            phi[3] = ph1[t1];
            uint32_t vh[4][4];
            #pragma unroll
            for (int g = 0; g < 4; g++) {
                const uint32_t voff = (ks * 16 + v_kv) * FROWB + (g * 16 + v_nc) * 2;
                LDSM_X4_T(vh[g][0], vh[g][1], vh[g][2], vh[g][3], st + FS_V + voff);
            }
            #pragma unroll
            for (int g = 0; g < 4; g++) {
                MMA_F16(O[2 * g],     phi, vh[g][0], vh[g][1]);
                MMA_F16(O[2 * g + 1], phi, vh[g][2], vh[g][3]);
            }
        }
        __syncthreads();
    }

    // ---- epilogue ----
    const float il0 = 1.f / l0, il1 = 1.f / l1;
    const size_t gr0 = (size_t)(b * SEQ + qr0) * DIM + h * HDIM;
    const size_t gr1 = gr0 + 8 * DIM;
    #pragma unroll
    for (int nt = 0; nt < 8; nt++) {
        const int col = nt * 8 + (lane & 3) * 2;
        *reinterpret_cast<uint32_t*>(ohi + gr0 + col) = pack_h2(O[nt][0] * il0, O[nt][1] * il0);
        *reinterpret_cast<uint32_t*>(ohi + gr1 + col) = pack_h2(O[nt][2] * il1, O[nt][3] * il1);
    }
}

// ==================== launch ================================================
extern "C" void kernel_launch(void* const* d_in, const int* in_sizes, int n_in,
                              void* d_out, int out_size)
{
    (void)in_sizes; (void)n_in; (void)out_size;
    const float* x     = (const float*)d_in[0];
    const float* ln1_g = (const float*)d_in[2];
    const float* ln1_b = (const float*)d_in[3];
    const float* ln2_g = (const float*)d_in[4];
    const float* ln2_b = (const float*)d_in[5];
    const float* qkv_w = (const float*)d_in[6];
    const float* out_w = (const float*)d_in[7];
    const float* out_b = (const float*)d_in[8];
    const float* fc1_w = (const float*)d_in[9];
    const float* fc1_b = (const float*)d_in[10];
    const float* fc2_w = (const float*)d_in[11];
    const float* fc2_b = (const float*)d_in[12];
    float* out = (float*)d_out;

    float *x2;
    __half *qkv, *h, *att, *ffn, *wq, *wo, *w1, *w2;
    cudaGetSymbolAddress((void**)&x2,  g_x2);
    cudaGetSymbolAddress((void**)&qkv, g_qkv);
    cudaGetSymbolAddress((void**)&h,   g_h);
    cudaGetSymbolAddress((void**)&att, g_att);
    cudaGetSymbolAddress((void**)&ffn, g_ffn);
    cudaGetSymbolAddress((void**)&wq,  g_wq);
    cudaGetSymbolAddress((void**)&wo,  g_wo);
    cudaGetSymbolAddress((void**)&w1,  g_w1);
    cudaGetSymbolAddress((void**)&w2,  g_w2);

    static int nsm = 0;
    if (!nsm) cudaDeviceGetAttribute(&nsm, cudaDevAttrMultiProcessorCount, 0);
    const int pgrid = 2 * nsm;

    cudaFuncSetAttribute(flash_tc_kernel,
                         cudaFuncAttributeMaxDynamicSharedMemorySize, FLASH_SMEM);
    cudaFuncSetAttribute(tc_gemm_kernel<EPI_QKV>,
                         cudaFuncAttributeMaxDynamicSharedMemorySize, GEMM_SMEM);
    cudaFuncSetAttribute(tc_gemm_kernel<EPI_BIAS_RESID>,
                         cudaFuncAttributeMaxDynamicSharedMemorySize, GEMM_SMEM);
    cudaFuncSetAttribute(tc_gemm_kernel<EPI_BIAS_GELU>,
                         cudaFuncAttributeMaxDynamicSharedMemorySize, GEMM_SMEM);

    wsplit_kernel<<<dim3(3 * DIM / 32, DIM / 32), 256>>>(qkv_w, wq, DIM, 3 * DIM);
    ln_kernel<<<MROWS, 256>>>(x, ln1_g, ln1_b, h);
    tc_gemm_kernel<EPI_QKV><<<pgrid, 256, GEMM_SMEM>>>(
        h, wq, nullptr, nullptr, nullptr, qkv, MROWS, 3 * DIM, DIM);
    flash_tc_kernel<<<dim3(SEQ / 128, BATCH * NHEAD), 256, FLASH_SMEM>>>(qkv, att);
    wsplit_kernel<<<dim3(DIM / 32, DIM / 32), 256>>>(out_w, wo, DIM, DIM);
    tc_gemm_kernel<EPI_BIAS_RESID><<<pgrid, 256, GEMM_SMEM>>>(
        att, wo, out_b, x, x2, nullptr, MROWS, DIM, DIM);
    ln_kernel<<<MROWS, 256>>>(x2, ln2_g, ln2_b, h);
    wsplit_kernel<<<dim3(FFDIM / 32, DIM / 32), 256>>>(fc1_w, w1, DIM, FFDIM);
    tc_gemm_kernel<EPI_BIAS_GELU><<<pgrid, 256, GEMM_SMEM>>>(
        h, w1, fc1_b, nullptr, nullptr, ffn, MROWS, FFDIM, DIM);
    wsplit_kernel<<<dim3(DIM / 32, FFDIM / 32), 256>>>(fc2_w, w2, FFDIM, DIM);
    tc_gemm_kernel<EPI_BIAS_RESID><<<pgrid, 256, GEMM_SMEM>>>(
        ffn, w2, fc2_b, x2, out, nullptr, MROWS, DIM, FFDIM);
}

// round 16
// speedup vs baseline: 1.0775x; 1.0775x over previous
#include <cuda_runtime.h>
#include <cuda_fp16.h>
#include <stdint.h>
#include <math.h>

// Problem constants
#define BATCH 4
#define SEQ   2048
#define DIM   1024
#define NHEAD 16
#define HDIM  64
#define FFDIM 4096
#define MROWS (BATCH*SEQ)   // 8192

// ==================== static device scratch (no runtime allocs) ============
__device__ float g_x2 [(size_t)MROWS * DIM];             // post-attn residual fp32
__device__ __half g_qkv[(size_t)MROWS * 3 * DIM];        // qkv fp16 (q scaled log2e/8)
__device__ __half g_h  [(size_t)MROWS * DIM];            // LN out fp16
__device__ __half g_att[(size_t)MROWS * DIM];            // attention out fp16
__device__ __half g_ffn[(size_t)MROWS * FFDIM];          // gelu(fc1) fp16
// transposed weights: [N, K] fp16
__device__ __half g_wq[(size_t)3*DIM * DIM];
__device__ __half g_wo[(size_t)DIM * DIM];
__device__ __half g_w1[(size_t)FFDIM * DIM];
__device__ __half g_w2[(size_t)DIM * FFDIM];

// ==================== helpers ==============================================
__device__ __forceinline__ uint32_t smem_u32(const void* p) {
    uint32_t a;
    asm("{ .reg .u64 t; cvta.to.shared.u64 t, %1; cvt.u32.u64 %0, t; }" : "=r"(a) : "l"(p));
    return a;
}

__device__ __forceinline__ float ex2f(float x) {
    float r;
    asm("ex2.approx.ftz.f32 %0, %1;" : "=f"(r) : "f"(x));
    return r;
}

// packed half2 exp2: d = 2^a (elementwise)
__device__ __forceinline__ uint32_t ex2_h2(uint32_t a) {
    uint32_t r;
    asm("ex2.approx.f16x2 %0, %1;" : "=r"(r) : "r"(a));
    return r;
}

__device__ __forceinline__ uint32_t hadd2u(uint32_t a, uint32_t b) {
    uint32_t r;
    asm("add.f16x2 %0, %1, %2;" : "=r"(r) : "r"(a), "r"(b));
    return r;
}

#define CP_ASYNC16(saddr, gptr) \
    asm volatile("cp.async.cg.shared.global [%0], [%1], 16;" \
        :: "r"(saddr), "l"((const void*)(gptr)))
#define CP_COMMIT() asm volatile("cp.async.commit_group;" ::: "memory")
#define CP_WAIT0()  asm volatile("cp.async.wait_group 0;" ::: "memory")
#define CP_WAIT1()  asm volatile("cp.async.wait_group 1;" ::: "memory")

#define LDSM_X4(r0, r1, r2, r3, addr) \
    asm volatile("ldmatrix.sync.aligned.m8n8.x4.shared.b16 {%0,%1,%2,%3}, [%4];" \
        : "=r"(r0), "=r"(r1), "=r"(r2), "=r"(r3) : "r"(addr))

#define LDSM_X4_T(r0, r1, r2, r3, addr) \
    asm volatile("ldmatrix.sync.aligned.m8n8.x4.trans.shared.b16 {%0,%1,%2,%3}, [%4];" \
        : "=r"(r0), "=r"(r1), "=r"(r2), "=r"(r3) : "r"(addr))

#define MMA_F16(d, a, b0v, b1v) \
    asm volatile("mma.sync.aligned.m16n8k16.row.col.f32.f16.f16.f32 " \
        "{%0,%1,%2,%3}, {%4,%5,%6,%7}, {%8,%9}, {%0,%1,%2,%3};" \
        : "+f"((d)[0]), "+f"((d)[1]), "+f"((d)[2]), "+f"((d)[3]) \
        : "r"((a)[0]), "r"((a)[1]), "r"((a)[2]), "r"((a)[3]), "r"(b0v), "r"(b1v))

__device__ __forceinline__ uint32_t pack_h2(float x, float y) {
    __half2 h = __floats2half2_rn(x, y);
    return *reinterpret_cast<uint32_t*>(&h);
}

// ==================== weight transpose + fp16 convert (vectorized) =========
__global__ void __launch_bounds__(256)
wsplit_kernel(const float* __restrict__ W, __half* __restrict__ Th, int K, int N)
{
    __shared__ float tile[32][33];
    const int bx = blockIdx.x, by = blockIdx.y;
    const int tx = threadIdx.x & 31, ty = threadIdx.x >> 5;
    #pragma unroll
    for (int r = 0; r < 32; r += 8) {
        const int k = by * 32 + ty + r, n = bx * 32 + tx;
        tile[ty + r][tx] = W[(size_t)k * N + n];
    }
    __syncthreads();
    const int kx = (threadIdx.x & 15) * 2;
    const int ny = threadIdx.x >> 4;
    #pragma unroll
    for (int r = 0; r < 32; r += 16) {
        const int n = bx * 32 + ny + r;
        const int k = by * 32 + kx;
        __half2 hv = __floats2half2_rn(tile[kx][ny + r], tile[kx + 1][ny + r]);
        *reinterpret_cast<__half2*>(Th + (size_t)n * K + k) = hv;
    }
}

// ==================== LayerNorm (emits fp16) ===============================
__global__ void __launch_bounds__(256)
ln_kernel(const float* __restrict__ x, const float* __restrict__ g,
          const float* __restrict__ bta, __half* __restrict__ ohi)
{
    const int row = blockIdx.x;
    const int t = threadIdx.x;
    const float* xr = x + (size_t)row * DIM;

    float4 v = *reinterpret_cast<const float4*>(xr + t * 4);
    float s = v.x + v.y + v.z + v.w;
    float q = v.x * v.x + v.y * v.y + v.z * v.z + v.w * v.w;

    #pragma unroll
    for (int o = 16; o; o >>= 1) {
        s += __shfl_xor_sync(0xffffffffu, s, o);
        q += __shfl_xor_sync(0xffffffffu, q, o);
    }
    __shared__ float red[2][8];
    const int w = t >> 5, l = t & 31;
    if (l == 0) { red[0][w] = s; red[1][w] = q; }
    __syncthreads();
    if (t < 32) {
        s = (t < 8) ? red[0][t] : 0.f;
        q = (t < 8) ? red[1][t] : 0.f;
        #pragma unroll
        for (int o = 4; o; o >>= 1) {
            s += __shfl_xor_sync(0xffffffffu, s, o);
            q += __shfl_xor_sync(0xffffffffu, q, o);
        }
        if (t == 0) { red[0][0] = s; red[1][0] = q; }
    }
    __syncthreads();
    const float mean = red[0][0] * (1.f / DIM);
    const float var  = red[1][0] * (1.f / DIM) - mean * mean;
    const float rstd = rsqrtf(var + 1e-5f);

    float4 gv = *reinterpret_cast<const float4*>(g + t * 4);
    float4 bv = *reinterpret_cast<const float4*>(bta + t * 4);
    const float o0 = (v.x - mean) * rstd * gv.x + bv.x;
    const float o1 = (v.y - mean) * rstd * gv.y + bv.y;
    const float o2 = (v.z - mean) * rstd * gv.z + bv.z;
    const float o3 = (v.w - mean) * rstd * gv.w + bv.w;

    const size_t off = (size_t)row * DIM + t * 4;
    *reinterpret_cast<uint32_t*>(ohi + off)     = pack_h2(o0, o1);
    *reinterpret_cast<uint32_t*>(ohi + off + 2) = pack_h2(o2, o3);
}

// ==================== mma.sync GEMM (fp16 1-pass, BK=64, 3-stage ring) =====
// C[M,N] = A[M,K] @ B^T, B [N,K] fp16 K-major. CTA 128x128, warp 64x32,
// 2 CTAs/SM. Next-chunk cp.async spread across the 4 ks steps.
enum { EPI_NONE = 0, EPI_BIAS_RESID = 1, EPI_BIAS_GELU = 2, EPI_QKV = 3 };

#define GROWB        144
#define STAGE_BYTES  (256 * GROWB)          // 36864
#define NSTAGE       3
#define GEMM_SMEM    (NSTAGE * STAGE_BYTES) // 110592
#define OFF_B        (128 * GROWB)          // 18432

template<int EPI>
__global__ void __launch_bounds__(256, 2)
tc_gemm_kernel(const __half* __restrict__ Ah, const __half* __restrict__ Bh,
               const float* __restrict__ bias, const float* __restrict__ R,
               float* __restrict__ Cf, __half* __restrict__ Ch,
               int N, int K)
{
    extern __shared__ char smem[];
    const uint32_t sb = smem_u32(smem);
    const int tid = threadIdx.x;
    const int lane = tid & 31, wid = tid >> 5;
    const int rowBase = blockIdx.y * 128;
    const int colBase = blockIdx.x * 128;

    float acc[4][4][4];
    #pragma unroll
    for (int mt = 0; mt < 4; mt++)
        #pragma unroll
        for (int nt = 0; nt < 4; nt++)
            #pragma unroll
            for (int r = 0; r < 4; r++) acc[mt][nt][r] = 0.f;

    // issue 2 of the 8 load slices for chunk c into stage buffer
    auto load_slice = [&](int c, int stage, int half) {
        const int kbase = c * 64;
        const uint32_t stbase = sb + stage * STAGE_BYTES;
        #pragma unroll
        for (int i = half * 2; i < half * 2 + 2; i++) {
            const int idx = tid + i * 256;        // 0..2047
            const int row = idx >> 3;             // 0..255
            const int q = idx & 7;
            const uint32_t so = stbase + row * GROWB + q * 16;
            const __half* gp = (row < 128)
                ? (Ah + (size_t)(rowBase + row) * K + kbase + q * 8)
                : (Bh + (size_t)(colBase + row - 128) * K + kbase + q * 8);
            CP_ASYNC16(so, gp);
        }
    };
    auto load_stage = [&](int c, int stage) {
        #pragma unroll
        for (int hf = 0; hf < 4; hf++) load_slice(c, stage, hf);
        CP_COMMIT();
    };

    const int nChunks = K >> 6;
    load_stage(0, 0);
    load_stage(1, 1);

    const uint32_t a_off0 = ((wid >> 2) * 64 + (lane & 15)) * GROWB + ((lane >> 4) * 8) * 2;
    const uint32_t b_off0 = OFF_B + ((wid & 3) * 32 + (lane & 7) + ((lane >> 4) << 3)) * GROWB
                          + (((lane >> 3) & 1) * 8) * 2;

    int stage = 0;
    for (int c = 0; c < nChunks; c++) {
        CP_WAIT1();
        __syncthreads();
        const bool more = (c + 2 < nChunks);
        int s2 = stage + 2; if (s2 >= NSTAGE) s2 -= NSTAGE;

        const uint32_t st = sb + stage * STAGE_BYTES;
        if (++stage == NSTAGE) stage = 0;

        #pragma unroll
        for (int ks = 0; ks < 4; ks++) {
            const uint32_t a_off = st + a_off0 + ks * 32;
            const uint32_t b_off = st + b_off0 + ks * 32;

            uint32_t a[4][4], b[8];
            #pragma unroll
            for (int mt = 0; mt < 4; mt++)
                LDSM_X4(a[mt][0], a[mt][1], a[mt][2], a[mt][3],
                        a_off + mt * (16 * GROWB));
            LDSM_X4(b[0], b[1], b[2], b[3], b_off);
            LDSM_X4(b[4], b[5], b[6], b[7], b_off + 16 * GROWB);
            // spread next-chunk global->shared issues across ks steps
            if (more) load_slice(c + 2, s2, ks);
            #pragma unroll
            for (int mt = 0; mt < 4; mt++)
                #pragma unroll
                for (int nt = 0; nt < 4; nt++)
                    MMA_F16(acc[mt][nt], a[mt], b[nt * 2], b[nt * 2 + 1]);
        }
        CP_COMMIT();
    }

    __syncthreads();

    // ------- epilogue -------
    #pragma unroll
    for (int mt = 0; mt < 4; mt++) {
        const int r0 = rowBase + (wid >> 2) * 64 + mt * 16 + (lane >> 2);
        const int r1 = r0 + 8;
        #pragma unroll
        for (int nt = 0; nt < 4; nt++) {
            const int col = colBase + (wid & 3) * 32 + nt * 8 + (lane & 3) * 2;
            float v0 = acc[mt][nt][0], v1 = acc[mt][nt][1];
            float v2 = acc[mt][nt][2], v3 = acc[mt][nt][3];
            if (EPI == EPI_BIAS_RESID || EPI == EPI_BIAS_GELU) {
                const float b0 = __ldg(bias + col), b1 = __ldg(bias + col + 1);
                v0 += b0; v1 += b1; v2 += b0; v3 += b1;
            }
            if (EPI == EPI_QKV) {
                // q: scale by log2(e)/8 so flash softmax can use exp2 directly
                const float sc = (col < DIM) ? 0.18033688011112042f : 1.0f;
                *reinterpret_cast<uint32_t*>(Ch + (size_t)r0 * N + col) = pack_h2(v0 * sc, v1 * sc);
                *reinterpret_cast<uint32_t*>(Ch + (size_t)r1 * N + col) = pack_h2(v2 * sc, v3 * sc);
            } else if (EPI == EPI_BIAS_GELU) {
                v0 = 0.5f * v0 * (1.f + erff(v0 * 0.70710678118654752f));
                v1 = 0.5f * v1 * (1.f + erff(v1 * 0.70710678118654752f));
                v2 = 0.5f * v2 * (1.f + erff(v2 * 0.70710678118654752f));
                v3 = 0.5f * v3 * (1.f + erff(v3 * 0.70710678118654752f));
                *reinterpret_cast<uint32_t*>(Ch + (size_t)r0 * N + col) = pack_h2(v0, v1);
                *reinterpret_cast<uint32_t*>(Ch + (size_t)r1 * N + col) = pack_h2(v2, v3);
            } else {
                if (EPI == EPI_BIAS_RESID) {
                    const float2 ra = *reinterpret_cast<const float2*>(R + (size_t)r0 * N + col);
                    const float2 rb = *reinterpret_cast<const float2*>(R + (size_t)r1 * N + col);
                    v0 += ra.x; v1 += ra.y; v2 += rb.x; v3 += rb.y;
                }
                float2 p0; p0.x = v0; p0.y = v1;
                float2 p1; p1.x = v2; p1.y = v3;
                *reinterpret_cast<float2*>(Cf + (size_t)r0 * N + col) = p0;
                *reinterpret_cast<float2*>(Cf + (size_t)r1 * N + col) = p1;
            }
        }
    }
}

// ==================== Flash attention (fp16 1-pass, f16x2 exp2 softmax) ====
// CTA: 128 q-rows x 64 kv per iter, 8 warps x 16 q-rows. Causal. 2 CTAs/SM.
// Scores in log2 domain (q pre-scaled by log2e/8); packed half2 exp2; P kept
// as half2 MMA fragments; row sums via HADD2 tree.
#define FROWB 144
#define FQ 0
#define FSTAGE0 (128*FROWB)                      // 18432
#define FS_K 0
#define FS_V (64*FROWB)
#define FSTAGE_BYTES (2*64*FROWB)                // 18432
#define FLASH_SMEM (FSTAGE0 + 2*FSTAGE_BYTES)    // 55296

__global__ void __launch_bounds__(256, 2)
flash_tc_kernel(const __half* __restrict__ qh, __half* __restrict__ ohi)
{
    extern __shared__ char smem[];
    const uint32_t sb = smem_u32(smem);
    const int qb = blockIdx.x;
    const int bh = blockIdx.y;
    const int b = bh >> 4, h = bh & 15;
    const int tid = threadIdx.x;
    const int lane = tid & 31, w = tid >> 5;
    const int rowStride = 3 * DIM;

    // load Q 128x64
    #pragma unroll
    for (int i = 0; i < 4; i++) {
        const int c = tid + i * 256;
        const int r = c >> 3, q = c & 7;
        const uint32_t so = r * FROWB + q * 16;
        const size_t go = (size_t)(b * SEQ + qb * 128 + r) * rowStride + h * HDIM + q * 8;
        CP_ASYNC16(sb + FQ + so, qh + go);
    }

    const int nkv = 2 * qb + 2;
    auto load_kv = [&](int j, int buf) {
        const uint32_t stb = sb + FSTAGE0 + buf * FSTAGE_BYTES;
        #pragma unroll
        for (int i = 0; i < 2; i++) {
            const int c = tid + i * 256;
            const int r = c >> 3, q = c & 7;
            const uint32_t so = r * FROWB + q * 16;
            const size_t gk = (size_t)(b * SEQ + j * 64 + r) * rowStride + DIM + h * HDIM + q * 8;
            CP_ASYNC16(stb + FS_K + so, qh + gk);
            CP_ASYNC16(stb + FS_V + so, qh + gk + DIM);
        }
        CP_COMMIT();
    };
    load_kv(0, 0);

    float O[8][4];
    #pragma unroll
    for (int nt = 0; nt < 8; nt++)
        #pragma unroll
        for (int r = 0; r < 4; r++) O[nt][r] = 0.f;
    float m0 = -1e30f, m1 = -1e30f, l0 = 0.f, l1 = 0.f;

    const int qr0 = qb * 128 + w * 16 + (lane >> 2);

    const int t8 = lane >> 3;
    const uint32_t q_row_off = (w * 16 + (lane & 15)) * FROWB;
    const uint32_t q_kadd = (lane >> 4) * 8;
    const uint32_t k_row = (t8 >> 1) * 8 + (lane & 7);
    const uint32_t k_hd = (t8 & 1) * 8;
    const uint32_t v_kv = (t8 & 1) * 8 + (lane & 7);
    const uint32_t v_nc = (t8 >> 1) * 8;

    for (int j = 0; j < nkv; j++) {
        CP_WAIT0();
        __syncthreads();
        if (j + 1 < nkv) load_kv(j + 1, (j + 1) & 1);
        const uint32_t st = sb + FSTAGE0 + (j & 1) * FSTAGE_BYTES;

        // ---- S = Q K^T (log2 domain) ----
        float s[8][4];
        #pragma unroll
        for (int nt = 0; nt < 8; nt++)
            #pragma unroll
            for (int r = 0; r < 4; r++) s[nt][r] = 0.f;

        #pragma unroll
        for (int ks = 0; ks < 4; ks++) {
            const uint32_t qoff = q_row_off + (ks * 16 + q_kadd) * 2;
            uint32_t a[4];
            LDSM_X4(a[0], a[1], a[2], a[3], sb + FQ + qoff);
            uint32_t kh[4][4];
            #pragma unroll
            for (int g = 0; g < 4; g++) {
                const uint32_t koff = (g * 16 + k_row) * FROWB + (ks * 16 + k_hd) * 2;
                LDSM_X4(kh[g][0], kh[g][1], kh[g][2], kh[g][3], st + FS_K + koff);
            }
            #pragma unroll
            for (int g = 0; g < 4; g++) {
                MMA_F16(s[2 * g],     a, kh[g][0], kh[g][1]);
                MMA_F16(s[2 * g + 1], a, kh[g][2], kh[g][3]);
            }
        }

        if (j >= 2 * qb) {
            const int kvb = j * 64;
            #pragma unroll
            for (int nt = 0; nt < 8; nt++) {
                const int kc = kvb + nt * 8 + (lane & 3) * 2;
                if (kc     > qr0)     s[nt][0] = -1e30f;
                if (kc + 1 > qr0)     s[nt][1] = -1e30f;
                if (kc     > qr0 + 8) s[nt][2] = -1e30f;
                if (kc + 1 > qr0 + 8) s[nt][3] = -1e30f;
            }
        }

        // ---- online softmax (packed f16x2 exp2) ----
        float mx0 = -1e30f, mx1 = -1e30f;
        #pragma unroll
        for (int nt = 0; nt < 8; nt++) {
            mx0 = fmaxf(mx0, fmaxf(s[nt][0], s[nt][1]));
            mx1 = fmaxf(mx1, fmaxf(s[nt][2], s[nt][3]));
        }
        mx0 = fmaxf(mx0, __shfl_xor_sync(0xffffffffu, mx0, 1));
        mx0 = fmaxf(mx0, __shfl_xor_sync(0xffffffffu, mx0, 2));
        mx1 = fmaxf(mx1, __shfl_xor_sync(0xffffffffu, mx1, 1));
        mx1 = fmaxf(mx1, __shfl_xor_sync(0xffffffffu, mx1, 2));
        const float nm0 = fmaxf(m0, mx0), nm1 = fmaxf(m1, mx1);
        const float sc0 = ex2f(m0 - nm0), sc1 = ex2f(m1 - nm1);
        m0 = nm0; m1 = nm1;

        // p = 2^(s - m), computed pairwise in half2; ph0[nt] = row0 pair,
        // ph1[nt] = row1 pair -> these ARE the PV A-fragments.
        uint32_t ph0[8], ph1[8];
        #pragma unroll
        for (int nt = 0; nt < 8; nt++) {
            ph0[nt] = ex2_h2(pack_h2(s[nt][0] - nm0, s[nt][1] - nm0));
            ph1[nt] = ex2_h2(pack_h2(s[nt][2] - nm1, s[nt][3] - nm1));
        }
        // row sums via HADD2 tree (values in [0,1], max sum 64 -> no overflow)
        uint32_t t0s = hadd2u(hadd2u(hadd2u(ph0[0], ph0[1]), hadd2u(ph0[2], ph0[3])),
                              hadd2u(hadd2u(ph0[4], ph0[5]), hadd2u(ph0[6], ph0[7])));
        uint32_t t1s = hadd2u(hadd2u(hadd2u(ph1[0], ph1[1]), hadd2u(ph1[2], ph1[3])),
                              hadd2u(hadd2u(ph1[4], ph1[5]), hadd2u(ph1[6], ph1[7])));
        const __half2 h0s = *reinterpret_cast<__half2*>(&t0s);
        const __half2 h1s = *reinterpret_cast<__half2*>(&t1s);
        float r0 = __low2float(h0s) + __high2float(h0s);
        float r1 = __low2float(h1s) + __high2float(h1s);
        r0 += __shfl_xor_sync(0xffffffffu, r0, 1);
        r0 += __shfl_xor_sync(0xffffffffu, r0, 2);
        r1 += __shfl_xor_sync(0xffffffffu, r1, 1);
        r1 += __shfl_xor_sync(0xffffffffu, r1, 2);
        l0 = l0 * sc0 + r0;
        l1 = l1 * sc1 + r1;
        #pragma unroll
        for (int nt = 0; nt < 8; nt++) {
            O[nt][0] *= sc0; O[nt][1] *= sc0;
            O[nt][2] *= sc1; O[nt][3] *= sc1;
        }

        // ---- O += P V (P fragments already packed) ----
        #pragma unroll
        for (int ks = 0; ks < 4; ks++) {
            const int t0 = 2 * ks, t1 = 2 * ks + 1;
            uint32_t phi[4];
            phi[0] = ph0[t0];
            phi[1] = ph1[t0];
            phi[2] = ph0[t1];
            phi[3] = ph1[t1];
            uint32_t vh[4][4];
            #pragma unroll
            for (int g = 0; g < 4; g++) {
                const uint32_t voff = (ks * 16 + v_kv) * FROWB + (g * 16 + v_nc) * 2;
                LDSM_X4_T(vh[g][0], vh[g][1], vh[g][2], vh[g][3], st + FS_V + voff);
            }
            #pragma unroll
            for (int g = 0; g < 4; g++) {
                MMA_F16(O[2 * g],     phi, vh[g][0], vh[g][1]);
                MMA_F16(O[2 * g + 1], phi, vh[g][2], vh[g][3]);
            }
        }
        __syncthreads();
    }

    // ---- epilogue ----
    const float il0 = 1.f / l0, il1 = 1.f / l1;
    const size_t gr0 = (size_t)(b * SEQ + qr0) * DIM + h * HDIM;
    const size_t gr1 = gr0 + 8 * DIM;
    #pragma unroll
    for (int nt = 0; nt < 8; nt++) {
        const int col = nt * 8 + (lane & 3) * 2;
        *reinterpret_cast<uint32_t*>(ohi + gr0 + col) = pack_h2(O[nt][0] * il0, O[nt][1] * il0);
        *reinterpret_cast<uint32_t*>(ohi + gr1 + col) = pack_h2(O[nt][2] * il1, O[nt][3] * il1);
    }
}

// ==================== launch ================================================
extern "C" void kernel_launch(void* const* d_in, const int* in_sizes, int n_in,
                              void* d_out, int out_size)
{
    (void)in_sizes; (void)n_in; (void)out_size;
    const float* x     = (const float*)d_in[0];
    const float* ln1_g = (const float*)d_in[2];
    const float* ln1_b = (const float*)d_in[3];
    const float* ln2_g = (const float*)d_in[4];
    const float* ln2_b = (const float*)d_in[5];
    const float* qkv_w = (const float*)d_in[6];
    const float* out_w = (const float*)d_in[7];
    const float* out_b = (const float*)d_in[8];
    const float* fc1_w = (const float*)d_in[9];
    const float* fc1_b = (const float*)d_in[10];
    const float* fc2_w = (const float*)d_in[11];
    const float* fc2_b = (const float*)d_in[12];
    float* out = (float*)d_out;

    float *x2;
    __half *qkv, *h, *att, *ffn, *wq, *wo, *w1, *w2;
    cudaGetSymbolAddress((void**)&x2,  g_x2);
    cudaGetSymbolAddress((void**)&qkv, g_qkv);
    cudaGetSymbolAddress((void**)&h,   g_h);
    cudaGetSymbolAddress((void**)&att, g_att);
    cudaGetSymbolAddress((void**)&ffn, g_ffn);
    cudaGetSymbolAddress((void**)&wq,  g_wq);
    cudaGetSymbolAddress((void**)&wo,  g_wo);
    cudaGetSymbolAddress((void**)&w1,  g_w1);
    cudaGetSymbolAddress((void**)&w2,  g_w2);

    cudaFuncSetAttribute(flash_tc_kernel,
                         cudaFuncAttributeMaxDynamicSharedMemorySize, FLASH_SMEM);
    cudaFuncSetAttribute(tc_gemm_kernel<EPI_QKV>,
                         cudaFuncAttributeMaxDynamicSharedMemorySize, GEMM_SMEM);
    cudaFuncSetAttribute(tc_gemm_kernel<EPI_BIAS_RESID>,
                         cudaFuncAttributeMaxDynamicSharedMemorySize, GEMM_SMEM);
    cudaFuncSetAttribute(tc_gemm_kernel<EPI_BIAS_GELU>,
                         cudaFuncAttributeMaxDynamicSharedMemorySize, GEMM_SMEM);

    wsplit_kernel<<<dim3(3 * DIM / 32, DIM / 32), 256>>>(qkv_w, wq, DIM, 3 * DIM);
    ln_kernel<<<MROWS, 256>>>(x, ln1_g, ln1_b, h);
    tc_gemm_kernel<EPI_QKV><<<dim3(3 * DIM / 128, MROWS / 128), 256, GEMM_SMEM>>>(
        h, wq, nullptr, nullptr, nullptr, qkv, 3 * DIM, DIM);
    flash_tc_kernel<<<dim3(SEQ / 128, BATCH * NHEAD), 256, FLASH_SMEM>>>(qkv, att);
    wsplit_kernel<<<dim3(DIM / 32, DIM / 32), 256>>>(out_w, wo, DIM, DIM);
    tc_gemm_kernel<EPI_BIAS_RESID><<<dim3(DIM / 128, MROWS / 128), 256, GEMM_SMEM>>>(
        att, wo, out_b, x, x2, nullptr, DIM, DIM);
    ln_kernel<<<MROWS, 256>>>(x2, ln2_g, ln2_b, h);
    wsplit_kernel<<<dim3(FFDIM / 32, DIM / 32), 256>>>(fc1_w, w1, DIM, FFDIM);
    tc_gemm_kernel<EPI_BIAS_GELU><<<dim3(FFDIM / 128, MROWS / 128), 256, GEMM_SMEM>>>(
        h, w1, fc1_b, nullptr, nullptr, ffn, FFDIM, DIM);
    wsplit_kernel<<<dim3(DIM / 32, FFDIM / 32), 256>>>(fc2_w, w2, FFDIM, DIM);
    tc_gemm_kernel<EPI_BIAS_RESID><<<dim3(DIM / 128, MROWS / 128), 256, GEMM_SMEM>>>(
        ffn, w2, fc2_b, x2, out, nullptr, DIM, FFDIM);
}

// round 17
// speedup vs baseline: 1.0896x; 1.0112x over previous
#include <cuda_runtime.h>
#include <cuda_fp16.h>
#include <stdint.h>
#include <math.h>

// Problem constants
#define BATCH 4
#define SEQ   2048
#define DIM   1024
#define NHEAD 16
#define HDIM  64
#define FFDIM 4096
#define MROWS (BATCH*SEQ)   // 8192

// ==================== static device scratch (no runtime allocs) ============
__device__ float g_x2 [(size_t)MROWS * DIM];             // post-attn residual fp32
__device__ __half g_qkv[(size_t)MROWS * 3 * DIM];        // qkv fp16 (q scaled log2e/8)
__device__ __half g_h  [(size_t)MROWS * DIM];            // LN out fp16
__device__ __half g_att[(size_t)MROWS * DIM];            // attention out fp16
__device__ __half g_ffn[(size_t)MROWS * FFDIM];          // gelu(fc1) fp16
// transposed weights: [N, K] fp16
__device__ __half g_wq[(size_t)3*DIM * DIM];
__device__ __half g_wo[(size_t)DIM * DIM];
__device__ __half g_w1[(size_t)FFDIM * DIM];
__device__ __half g_w2[(size_t)DIM * FFDIM];

// ==================== host-side aux stream/events (created at load) ========
struct AuxResources {
    cudaStream_t s;
    cudaEvent_t fork, ewq, ewo, ew1, ew2;
    AuxResources() {
        cudaStreamCreateWithFlags(&s, cudaStreamNonBlocking);
        cudaEventCreateWithFlags(&fork, cudaEventDisableTiming);
        cudaEventCreateWithFlags(&ewq,  cudaEventDisableTiming);
        cudaEventCreateWithFlags(&ewo,  cudaEventDisableTiming);
        cudaEventCreateWithFlags(&ew1,  cudaEventDisableTiming);
        cudaEventCreateWithFlags(&ew2,  cudaEventDisableTiming);
    }
};
static AuxResources g_aux;

// ==================== helpers ==============================================
__device__ __forceinline__ uint32_t smem_u32(const void* p) {
    uint32_t a;
    asm("{ .reg .u64 t; cvta.to.shared.u64 t, %1; cvt.u32.u64 %0, t; }" : "=r"(a) : "l"(p));
    return a;
}

__device__ __forceinline__ float ex2f(float x) {
    float r;
    asm("ex2.approx.ftz.f32 %0, %1;" : "=f"(r) : "f"(x));
    return r;
}

// packed half2 exp2: d = 2^a (elementwise)
__device__ __forceinline__ uint32_t ex2_h2(uint32_t a) {
    uint32_t r;
    asm("ex2.approx.f16x2 %0, %1;" : "=r"(r) : "r"(a));
    return r;
}

__device__ __forceinline__ uint32_t hadd2u(uint32_t a, uint32_t b) {
    uint32_t r;
    asm("add.f16x2 %0, %1, %2;" : "=r"(r) : "r"(a), "r"(b));
    return r;
}

#define CP_ASYNC16(saddr, gptr) \
    asm volatile("cp.async.cg.shared.global [%0], [%1], 16;" \
        :: "r"(saddr), "l"((const void*)(gptr)))
#define CP_COMMIT() asm volatile("cp.async.commit_group;" ::: "memory")
#define CP_WAIT0()  asm volatile("cp.async.wait_group 0;" ::: "memory")
#define CP_WAIT1()  asm volatile("cp.async.wait_group 1;" ::: "memory")

#define LDSM_X4(r0, r1, r2, r3, addr) \
    asm volatile("ldmatrix.sync.aligned.m8n8.x4.shared.b16 {%0,%1,%2,%3}, [%4];" \
        : "=r"(r0), "=r"(r1), "=r"(r2), "=r"(r3) : "r"(addr))

#define LDSM_X4_T(r0, r1, r2, r3, addr) \
    asm volatile("ldmatrix.sync.aligned.m8n8.x4.trans.shared.b16 {%0,%1,%2,%3}, [%4];" \
        : "=r"(r0), "=r"(r1), "=r"(r2), "=r"(r3) : "r"(addr))

#define MMA_F16(d, a, b0v, b1v) \
    asm volatile("mma.sync.aligned.m16n8k16.row.col.f32.f16.f16.f32 " \
        "{%0,%1,%2,%3}, {%4,%5,%6,%7}, {%8,%9}, {%0,%1,%2,%3};" \
        : "+f"((d)[0]), "+f"((d)[1]), "+f"((d)[2]), "+f"((d)[3]) \
        : "r"((a)[0]), "r"((a)[1]), "r"((a)[2]), "r"((a)[3]), "r"(b0v), "r"(b1v))

__device__ __forceinline__ uint32_t pack_h2(float x, float y) {
    __half2 h = __floats2half2_rn(x, y);
    return *reinterpret_cast<uint32_t*>(&h);
}

// ==================== weight transpose + fp16 convert (vectorized) =========
__global__ void __launch_bounds__(256)
wsplit_kernel(const float* __restrict__ W, __half* __restrict__ Th, int K, int N)
{
    __shared__ float tile[32][33];
    const int bx = blockIdx.x, by = blockIdx.y;
    const int tx = threadIdx.x & 31, ty = threadIdx.x >> 5;
    #pragma unroll
    for (int r = 0; r < 32; r += 8) {
        const int k = by * 32 + ty + r, n = bx * 32 + tx;
        tile[ty + r][tx] = W[(size_t)k * N + n];
    }
    __syncthreads();
    const int kx = (threadIdx.x & 15) * 2;
    const int ny = threadIdx.x >> 4;
    #pragma unroll
    for (int r = 0; r < 32; r += 16) {
        const int n = bx * 32 + ny + r;
        const int k = by * 32 + kx;
        __half2 hv = __floats2half2_rn(tile[kx][ny + r], tile[kx + 1][ny + r]);
        *reinterpret_cast<__half2*>(Th + (size_t)n * K + k) = hv;
    }
}

// ==================== LayerNorm (emits fp16) ===============================
__global__ void __launch_bounds__(256)
ln_kernel(const float* __restrict__ x, const float* __restrict__ g,
          const float* __restrict__ bta, __half* __restrict__ ohi)
{
    const int row = blockIdx.x;
    const int t = threadIdx.x;
    const float* xr = x + (size_t)row * DIM;

    float4 v = *reinterpret_cast<const float4*>(xr + t * 4);
    float s = v.x + v.y + v.z + v.w;
    float q = v.x * v.x + v.y * v.y + v.z * v.z + v.w * v.w;

    #pragma unroll
    for (int o = 16; o; o >>= 1) {
        s += __shfl_xor_sync(0xffffffffu, s, o);
        q += __shfl_xor_sync(0xffffffffu, q, o);
    }
    __shared__ float red[2][8];
    const int w = t >> 5, l = t & 31;
    if (l == 0) { red[0][w] = s; red[1][w] = q; }
    __syncthreads();
    if (t < 32) {
        s = (t < 8) ? red[0][t] : 0.f;
        q = (t < 8) ? red[1][t] : 0.f;
        #pragma unroll
        for (int o = 4; o; o >>= 1) {
            s += __shfl_xor_sync(0xffffffffu, s, o);
            q += __shfl_xor_sync(0xffffffffu, q, o);
        }
        if (t == 0) { red[0][0] = s; red[1][0] = q; }
    }
    __syncthreads();
    const float mean = red[0][0] * (1.f / DIM);
    const float var  = red[1][0] * (1.f / DIM) - mean * mean;
    const float rstd = rsqrtf(var + 1e-5f);

    float4 gv = *reinterpret_cast<const float4*>(g + t * 4);
    float4 bv = *reinterpret_cast<const float4*>(bta + t * 4);
    const float o0 = (v.x - mean) * rstd * gv.x + bv.x;
    const float o1 = (v.y - mean) * rstd * gv.y + bv.y;
    const float o2 = (v.z - mean) * rstd * gv.z + bv.z;
    const float o3 = (v.w - mean) * rstd * gv.w + bv.w;

    const size_t off = (size_t)row * DIM + t * 4;
    *reinterpret_cast<uint32_t*>(ohi + off)     = pack_h2(o0, o1);
    *reinterpret_cast<uint32_t*>(ohi + off + 2) = pack_h2(o2, o3);
}

// ==================== mma.sync GEMM (fp16 1-pass, BK=64, 3-stage ring) =====
// C[M,N] = A[M,K] @ B^T, B [N,K] fp16 K-major. CTA 128x128, warp 64x32,
// 2 CTAs/SM. Next-chunk cp.async spread across the 4 ks steps.
enum { EPI_NONE = 0, EPI_BIAS_RESID = 1, EPI_BIAS_GELU = 2, EPI_QKV = 3 };

#define GROWB        144
#define STAGE_BYTES  (256 * GROWB)          // 36864
#define NSTAGE       3
#define GEMM_SMEM    (NSTAGE * STAGE_BYTES) // 110592
#define OFF_B        (128 * GROWB)          // 18432

template<int EPI>
__global__ void __launch_bounds__(256, 2)
tc_gemm_kernel(const __half* __restrict__ Ah, const __half* __restrict__ Bh,
               const float* __restrict__ bias, const float* __restrict__ R,
               float* __restrict__ Cf, __half* __restrict__ Ch,
               int N, int K)
{
    extern __shared__ char smem[];
    const uint32_t sb = smem_u32(smem);
    const int tid = threadIdx.x;
    const int lane = tid & 31, wid = tid >> 5;
    const int rowBase = blockIdx.y * 128;
    const int colBase = blockIdx.x * 128;

    float acc[4][4][4];
    #pragma unroll
    for (int mt = 0; mt < 4; mt++)
        #pragma unroll
        for (int nt = 0; nt < 4; nt++)
            #pragma unroll
            for (int r = 0; r < 4; r++) acc[mt][nt][r] = 0.f;

    // issue 2 of the 8 load slices for chunk c into stage buffer
    auto load_slice = [&](int c, int stage, int half) {
        const int kbase = c * 64;
        const uint32_t stbase = sb + stage * STAGE_BYTES;
        #pragma unroll
        for (int i = half * 2; i < half * 2 + 2; i++) {
            const int idx = tid + i * 256;        // 0..2047
            const int row = idx >> 3;             // 0..255
            const int q = idx & 7;
            const uint32_t so = stbase + row * GROWB + q * 16;
            const __half* gp = (row < 128)
                ? (Ah + (size_t)(rowBase + row) * K + kbase + q * 8)
                : (Bh + (size_t)(colBase + row - 128) * K + kbase + q * 8);
            CP_ASYNC16(so, gp);
        }
    };
    auto load_stage = [&](int c, int stage) {
        #pragma unroll
        for (int hf = 0; hf < 4; hf++) load_slice(c, stage, hf);
        CP_COMMIT();
    };

    const int nChunks = K >> 6;
    load_stage(0, 0);
    load_stage(1, 1);

    const uint32_t a_off0 = ((wid >> 2) * 64 + (lane & 15)) * GROWB + ((lane >> 4) * 8) * 2;
    const uint32_t b_off0 = OFF_B + ((wid & 3) * 32 + (lane & 7) + ((lane >> 4) << 3)) * GROWB
                          + (((lane >> 3) & 1) * 8) * 2;

    int stage = 0;
    for (int c = 0; c < nChunks; c++) {
        CP_WAIT1();
        __syncthreads();
        const bool more = (c + 2 < nChunks);
        int s2 = stage + 2; if (s2 >= NSTAGE) s2 -= NSTAGE;

        const uint32_t st = sb + stage * STAGE_BYTES;
        if (++stage == NSTAGE) stage = 0;

        #pragma unroll
        for (int ks = 0; ks < 4; ks++) {
            const uint32_t a_off = st + a_off0 + ks * 32;
            const uint32_t b_off = st + b_off0 + ks * 32;

            uint32_t a[4][4], b[8];
            #pragma unroll
            for (int mt = 0; mt < 4; mt++)
                LDSM_X4(a[mt][0], a[mt][1], a[mt][2], a[mt][3],
                        a_off + mt * (16 * GROWB));
            LDSM_X4(b[0], b[1], b[2], b[3], b_off);
            LDSM_X4(b[4], b[5], b[6], b[7], b_off + 16 * GROWB);
            // spread next-chunk global->shared issues across ks steps
            if (more) load_slice(c + 2, s2, ks);
            #pragma unroll
            for (int mt = 0; mt < 4; mt++)
                #pragma unroll
                for (int nt = 0; nt < 4; nt++)
                    MMA_F16(acc[mt][nt], a[mt], b[nt * 2], b[nt * 2 + 1]);
        }
        CP_COMMIT();
    }

    __syncthreads();

    // ------- epilogue -------
    #pragma unroll
    for (int mt = 0; mt < 4; mt++) {
        const int r0 = rowBase + (wid >> 2) * 64 + mt * 16 + (lane >> 2);
        const int r1 = r0 + 8;
        #pragma unroll
        for (int nt = 0; nt < 4; nt++) {
            const int col = colBase + (wid & 3) * 32 + nt * 8 + (lane & 3) * 2;
            float v0 = acc[mt][nt][0], v1 = acc[mt][nt][1];
            float v2 = acc[mt][nt][2], v3 = acc[mt][nt][3];
            if (EPI == EPI_BIAS_RESID || EPI == EPI_BIAS_GELU) {
                const float b0 = __ldg(bias + col), b1 = __ldg(bias + col + 1);
                v0 += b0; v1 += b1; v2 += b0; v3 += b1;
            }
            if (EPI == EPI_QKV) {
                // q: scale by log2(e)/8 so flash softmax can use exp2 directly
                const float sc = (col < DIM) ? 0.18033688011112042f : 1.0f;
                *reinterpret_cast<uint32_t*>(Ch + (size_t)r0 * N + col) = pack_h2(v0 * sc, v1 * sc);
                *reinterpret_cast<uint32_t*>(Ch + (size_t)r1 * N + col) = pack_h2(v2 * sc, v3 * sc);
            } else if (EPI == EPI_BIAS_GELU) {
                v0 = 0.5f * v0 * (1.f + erff(v0 * 0.70710678118654752f));
                v1 = 0.5f * v1 * (1.f + erff(v1 * 0.70710678118654752f));
                v2 = 0.5f * v2 * (1.f + erff(v2 * 0.70710678118654752f));
                v3 = 0.5f * v3 * (1.f + erff(v3 * 0.70710678118654752f));
                *reinterpret_cast<uint32_t*>(Ch + (size_t)r0 * N + col) = pack_h2(v0, v1);
                *reinterpret_cast<uint32_t*>(Ch + (size_t)r1 * N + col) = pack_h2(v2, v3);
            } else {
                if (EPI == EPI_BIAS_RESID) {
                    const float2 ra = *reinterpret_cast<const float2*>(R + (size_t)r0 * N + col);
                    const float2 rb = *reinterpret_cast<const float2*>(R + (size_t)r1 * N + col);
                    v0 += ra.x; v1 += ra.y; v2 += rb.x; v3 += rb.y;
                }
                float2 p0; p0.x = v0; p0.y = v1;
                float2 p1; p1.x = v2; p1.y = v3;
                *reinterpret_cast<float2*>(Cf + (size_t)r0 * N + col) = p0;
                *reinterpret_cast<float2*>(Cf + (size_t)r1 * N + col) = p1;
            }
        }
    }
}

// ==================== Flash attention (fp16 1-pass, f16x2 exp2 softmax) ====
// CTA: 128 q-rows x 64 kv per iter, 8 warps x 16 q-rows. Causal. 2 CTAs/SM.
#define FROWB 144
#define FQ 0
#define FSTAGE0 (128*FROWB)                      // 18432
#define FS_K 0
#define FS_V (64*FROWB)
#define FSTAGE_BYTES (2*64*FROWB)                // 18432
#define FLASH_SMEM (FSTAGE0 + 2*FSTAGE_BYTES)    // 55296

__global__ void __launch_bounds__(256, 2)
flash_tc_kernel(const __half* __restrict__ qh, __half* __restrict__ ohi)
{
    extern __shared__ char smem[];
    const uint32_t sb = smem_u32(smem);
    const int qb = blockIdx.x;
    const int bh = blockIdx.y;
    const int b = bh >> 4, h = bh & 15;
    const int tid = threadIdx.x;
    const int lane = tid & 31, w = tid >> 5;
    const int rowStride = 3 * DIM;

    // load Q 128x64
    #pragma unroll
    for (int i = 0; i < 4; i++) {
        const int c = tid + i * 256;
        const int r = c >> 3, q = c & 7;
        const uint32_t so = r * FROWB + q * 16;
        const size_t go = (size_t)(b * SEQ + qb * 128 + r) * rowStride + h * HDIM + q * 8;
        CP_ASYNC16(sb + FQ + so, qh + go);
    }

    const int nkv = 2 * qb + 2;
    auto load_kv = [&](int j, int buf) {
        const uint32_t stb = sb + FSTAGE0 + buf * FSTAGE_BYTES;
        #pragma unroll
        for (int i = 0; i < 2; i++) {
            const int c = tid + i * 256;
            const int r = c >> 3, q = c & 7;
            const uint32_t so = r * FROWB + q * 16;
            const size_t gk = (size_t)(b * SEQ + j * 64 + r) * rowStride + DIM + h * HDIM + q * 8;
            CP_ASYNC16(stb + FS_K + so, qh + gk);
            CP_ASYNC16(stb + FS_V + so, qh + gk + DIM);
        }
        CP_COMMIT();
    };
    load_kv(0, 0);

    float O[8][4];
    #pragma unroll
    for (int nt = 0; nt < 8; nt++)
        #pragma unroll
        for (int r = 0; r < 4; r++) O[nt][r] = 0.f;
    float m0 = -1e30f, m1 = -1e30f, l0 = 0.f, l1 = 0.f;

    const int qr0 = qb * 128 + w * 16 + (lane >> 2);

    const int t8 = lane >> 3;
    const uint32_t q_row_off = (w * 16 + (lane & 15)) * FROWB;
    const uint32_t q_kadd = (lane >> 4) * 8;
    const uint32_t k_row = (t8 >> 1) * 8 + (lane & 7);
    const uint32_t k_hd = (t8 & 1) * 8;
    const uint32_t v_kv = (t8 & 1) * 8 + (lane & 7);
    const uint32_t v_nc = (t8 >> 1) * 8;

    for (int j = 0; j < nkv; j++) {
        CP_WAIT0();
        __syncthreads();
        if (j + 1 < nkv) load_kv(j + 1, (j + 1) & 1);
        const uint32_t st = sb + FSTAGE0 + (j & 1) * FSTAGE_BYTES;

        // ---- S = Q K^T (log2 domain) ----
        float s[8][4];
        #pragma unroll
        for (int nt = 0; nt < 8; nt++)
            #pragma unroll
            for (int r = 0; r < 4; r++) s[nt][r] = 0.f;

        #pragma unroll
        for (int ks = 0; ks < 4; ks++) {
            const uint32_t qoff = q_row_off + (ks * 16 + q_kadd) * 2;
            uint32_t a[4];
            LDSM_X4(a[0], a[1], a[2], a[3], sb + FQ + qoff);
            uint32_t kh[4][4];
            #pragma unroll
            for (int g = 0; g < 4; g++) {
                const uint32_t koff = (g * 16 + k_row) * FROWB + (ks * 16 + k_hd) * 2;
                LDSM_X4(kh[g][0], kh[g][1], kh[g][2], kh[g][3], st + FS_K + koff);
            }
            #pragma unroll
            for (int g = 0; g < 4; g++) {
                MMA_F16(s[2 * g],     a, kh[g][0], kh[g][1]);
                MMA_F16(s[2 * g + 1], a, kh[g][2], kh[g][3]);
            }
        }

        if (j >= 2 * qb) {
            const int kvb = j * 64;
            #pragma unroll
            for (int nt = 0; nt < 8; nt++) {
                const int kc = kvb + nt * 8 + (lane & 3) * 2;
                if (kc     > qr0)     s[nt][0] = -1e30f;
                if (kc + 1 > qr0)     s[nt][1] = -1e30f;
                if (kc     > qr0 + 8) s[nt][2] = -1e30f;
                if (kc + 1 > qr0 + 8) s[nt][3] = -1e30f;
            }
        }

        // ---- online softmax (packed f16x2 exp2) ----
        float mx0 = -1e30f, mx1 = -1e30f;
        #pragma unroll
        for (int nt = 0; nt < 8; nt++) {
            mx0 = fmaxf(mx0, fmaxf(s[nt][0], s[nt][1]));
            mx1 = fmaxf(mx1, fmaxf(s[nt][2], s[nt][3]));
        }
        mx0 = fmaxf(mx0, __shfl_xor_sync(0xffffffffu, mx0, 1));
        mx0 = fmaxf(mx0, __shfl_xor_sync(0xffffffffu, mx0, 2));
        mx1 = fmaxf(mx1, __shfl_xor_sync(0xffffffffu, mx1, 1));
        mx1 = fmaxf(mx1, __shfl_xor_sync(0xffffffffu, mx1, 2));
        const float nm0 = fmaxf(m0, mx0), nm1 = fmaxf(m1, mx1);
        const float sc0 = ex2f(m0 - nm0), sc1 = ex2f(m1 - nm1);
        m0 = nm0; m1 = nm1;

        uint32_t ph0[8], ph1[8];
        #pragma unroll
        for (int nt = 0; nt < 8; nt++) {
            ph0[nt] = ex2_h2(pack_h2(s[nt][0] - nm0, s[nt][1] - nm0));
            ph1[nt] = ex2_h2(pack_h2(s[nt][2] - nm1, s[nt][3] - nm1));
        }
        uint32_t t0s = hadd2u(hadd2u(hadd2u(ph0[0], ph0[1]), hadd2u(ph0[2], ph0[3])),
                              hadd2u(hadd2u(ph0[4], ph0[5]), hadd2u(ph0[6], ph0[7])));
        uint32_t t1s = hadd2u(hadd2u(hadd2u(ph1[0], ph1[1]), hadd2u(ph1[2], ph1[3])),
                              hadd2u(hadd2u(ph1[4], ph1[5]), hadd2u(ph1[6], ph1[7])));
        const __half2 h0s = *reinterpret_cast<__half2*>(&t0s);
        const __half2 h1s = *reinterpret_cast<__half2*>(&t1s);
        float r0 = __low2float(h0s) + __high2float(h0s);
        float r1 = __low2float(h1s) + __high2float(h1s);
        r0 += __shfl_xor_sync(0xffffffffu, r0, 1);
        r0 += __shfl_xor_sync(0xffffffffu, r0, 2);
        r1 += __shfl_xor_sync(0xffffffffu, r1, 1);
        r1 += __shfl_xor_sync(0xffffffffu, r1, 2);
        l0 = l0 * sc0 + r0;
        l1 = l1 * sc1 + r1;
        #pragma unroll
        for (int nt = 0; nt < 8; nt++) {
            O[nt][0] *= sc0; O[nt][1] *= sc0;
            O[nt][2] *= sc1; O[nt][3] *= sc1;
        }

        // ---- O += P V (P fragments already packed) ----
        #pragma unroll
        for (int ks = 0; ks < 4; ks++) {
            const int t0 = 2 * ks, t1 = 2 * ks + 1;
            uint32_t phi[4];
            phi[0] = ph0[t0];
            phi[1] = ph1[t0];
            phi[2] = ph0[t1];
            phi[3] = ph1[t1];
            uint32_t vh[4][4];
            #pragma unroll
            for (int g = 0; g < 4; g++) {
                const uint32_t voff = (ks * 16 + v_kv) * FROWB + (g * 16 + v_nc) * 2;
                LDSM_X4_T(vh[g][0], vh[g][1], vh[g][2], vh[g][3], st + FS_V + voff);
            }
            #pragma unroll
            for (int g = 0; g < 4; g++) {
                MMA_F16(O[2 * g],     phi, vh[g][0], vh[g][1]);
                MMA_F16(O[2 * g + 1], phi, vh[g][2], vh[g][3]);
            }
        }
        __syncthreads();
    }

    // ---- epilogue ----
    const float il0 = 1.f / l0, il1 = 1.f / l1;
    const size_t gr0 = (size_t)(b * SEQ + qr0) * DIM + h * HDIM;
    const size_t gr1 = gr0 + 8 * DIM;
    #pragma unroll
    for (int nt = 0; nt < 8; nt++) {
        const int col = nt * 8 + (lane & 3) * 2;
        *reinterpret_cast<uint32_t*>(ohi + gr0 + col) = pack_h2(O[nt][0] * il0, O[nt][1] * il0);
        *reinterpret_cast<uint32_t*>(ohi + gr1 + col) = pack_h2(O[nt][2] * il1, O[nt][3] * il1);
    }
}

// ==================== launch ================================================
extern "C" void kernel_launch(void* const* d_in, const int* in_sizes, int n_in,
                              void* d_out, int out_size)
{
    (void)in_sizes; (void)n_in; (void)out_size;
    const float* x     = (const float*)d_in[0];
    const float* ln1_g = (const float*)d_in[2];
    const float* ln1_b = (const float*)d_in[3];
    const float* ln2_g = (const float*)d_in[4];
    const float* ln2_b = (const float*)d_in[5];
    const float* qkv_w = (const float*)d_in[6];
    const float* out_w = (const float*)d_in[7];
    const float* out_b = (const float*)d_in[8];
    const float* fc1_w = (const float*)d_in[9];
    const float* fc1_b = (const float*)d_in[10];
    const float* fc2_w = (const float*)d_in[11];
    const float* fc2_b = (const float*)d_in[12];
    float* out = (float*)d_out;

    float *x2;
    __half *qkv, *h, *att, *ffn, *wq, *wo, *w1, *w2;
    cudaGetSymbolAddress((void**)&x2,  g_x2);
    cudaGetSymbolAddress((void**)&qkv, g_qkv);
    cudaGetSymbolAddress((void**)&h,   g_h);
    cudaGetSymbolAddress((void**)&att, g_att);
    cudaGetSymbolAddress((void**)&ffn, g_ffn);
    cudaGetSymbolAddress((void**)&wq,  g_wq);
    cudaGetSymbolAddress((void**)&wo,  g_wo);
    cudaGetSymbolAddress((void**)&w1,  g_w1);
    cudaGetSymbolAddress((void**)&w2,  g_w2);

    cudaFuncSetAttribute(flash_tc_kernel,
                         cudaFuncAttributeMaxDynamicSharedMemorySize, FLASH_SMEM);
    cudaFuncSetAttribute(tc_gemm_kernel<EPI_QKV>,
                         cudaFuncAttributeMaxDynamicSharedMemorySize, GEMM_SMEM);
    cudaFuncSetAttribute(tc_gemm_kernel<EPI_BIAS_RESID>,
                         cudaFuncAttributeMaxDynamicSharedMemorySize, GEMM_SMEM);
    cudaFuncSetAttribute(tc_gemm_kernel<EPI_BIAS_GELU>,
                         cudaFuncAttributeMaxDynamicSharedMemorySize, GEMM_SMEM);

    // fork: weight conversions run on the aux stream, overlapping the main chain
    cudaEventRecord(g_aux.fork, 0);
    cudaStreamWaitEvent(g_aux.s, g_aux.fork, 0);
    wsplit_kernel<<<dim3(3 * DIM / 32, DIM / 32), 256, 0, g_aux.s>>>(qkv_w, wq, DIM, 3 * DIM);
    cudaEventRecord(g_aux.ewq, g_aux.s);
    wsplit_kernel<<<dim3(DIM / 32, DIM / 32), 256, 0, g_aux.s>>>(out_w, wo, DIM, DIM);
    cudaEventRecord(g_aux.ewo, g_aux.s);
    wsplit_kernel<<<dim3(FFDIM / 32, DIM / 32), 256, 0, g_aux.s>>>(fc1_w, w1, DIM, FFDIM);
    cudaEventRecord(g_aux.ew1, g_aux.s);
    wsplit_kernel<<<dim3(DIM / 32, FFDIM / 32), 256, 0, g_aux.s>>>(fc2_w, w2, FFDIM, DIM);
    cudaEventRecord(g_aux.ew2, g_aux.s);

    // main chain (default stream); LN1 overlaps the weight conversions
    ln_kernel<<<MROWS, 256>>>(x, ln1_g, ln1_b, h);
    cudaStreamWaitEvent(0, g_aux.ewq, 0);
    tc_gemm_kernel<EPI_QKV><<<dim3(3 * DIM / 128, MROWS / 128), 256, GEMM_SMEM>>>(
        h, wq, nullptr, nullptr, nullptr, qkv, 3 * DIM, DIM);
    flash_tc_kernel<<<dim3(SEQ / 128, BATCH * NHEAD), 256, FLASH_SMEM>>>(qkv, att);
    cudaStreamWaitEvent(0, g_aux.ewo, 0);
    tc_gemm_kernel<EPI_BIAS_RESID><<<dim3(DIM / 128, MROWS / 128), 256, GEMM_SMEM>>>(
        att, wo, out_b, x, x2, nullptr, DIM, DIM);
    ln_kernel<<<MROWS, 256>>>(x2, ln2_g, ln2_b, h);
    cudaStreamWaitEvent(0, g_aux.ew1, 0);
    tc_gemm_kernel<EPI_BIAS_GELU><<<dim3(FFDIM / 128, MROWS / 128), 256, GEMM_SMEM>>>(
        h, w1, fc1_b, nullptr, nullptr, ffn, FFDIM, DIM);
    cudaStreamWaitEvent(0, g_aux.ew2, 0);
    tc_gemm_kernel<EPI_BIAS_RESID><<<dim3(DIM / 128, MROWS / 128), 256, GEMM_SMEM>>>(
        ffn, w2, fc2_b, x2, out, nullptr, DIM, FFDIM);
}